// round 4
// baseline (speedup 1.0000x reference)
#include <cuda_runtime.h>

#define TX 32
#define TY 16
#define ZC 32
#define NDIM 128
#define PLANE 16384          // 128*128
#define CS 2097152           // 128^3 (channel stride)
#define ROWL 34              // TX+2
#define COLH 18              // TY+2
#define NTHREADS (TX*TY)

__device__ double g_acc;

__global__ void zero_acc_kernel() { g_acc = 0.0; }

// Compute the 7 2D-filtered values at (ty,tx) from a halo plane in smem.
// s=[1,2,1], d=[-1,0,1], o=[1,1,1]
// H[0]=s_y d_x  H[1]=d_y s_x  H[2]=o_y d_x  H[3]=d_y o_x
// H[4]=s_y s_x  H[5]=o_y s_x  H[6]=s_y o_x
__device__ __forceinline__ void computeH(const float* __restrict__ sm,
                                         int ty, int tx, float* H) {
    const float* r0 = sm + ty * ROWL + tx;
    const float* r1 = r0 + ROWL;
    const float* r2 = r1 + ROWL;
    float a00 = r0[0], a01 = r0[1], a02 = r0[2];
    float a10 = r1[0], a11 = r1[1], a12 = r1[2];
    float a20 = r2[0], a21 = r2[1], a22 = r2[2];
    // column (y) filters at dx = -1,0,+1
    float t0 = a00 + a20, t1 = a01 + a21, t2 = a02 + a22;
    float sc0 = fmaf(2.f, a10, t0), sc1 = fmaf(2.f, a11, t1), sc2 = fmaf(2.f, a12, t2);
    float oc0 = t0 + a10, oc1 = t1 + a11, oc2 = t2 + a12;
    float dc0 = a20 - a00, dc1 = a21 - a01, dc2 = a22 - a02;
    float td = dc0 + dc2, ts = sc0 + sc2, to = oc0 + oc2;
    H[0] = sc2 - sc0;
    H[1] = fmaf(2.f, dc1, td);
    H[2] = oc2 - oc0;
    H[3] = td + dc1;
    H[4] = fmaf(2.f, sc1, ts);
    H[5] = fmaf(2.f, oc1, to);
    H[6] = ts + sc1;
}

// Combine z-ring (A=z-1, B=z, C=z+1) into edge magnitude * 0.5 (C=2 channels).
__device__ __forceinline__ float edgeFromH(const float* A, const float* B, const float* C) {
    float t;
    t = A[0] + C[0];
    float Gssd = fmaf(2.f, B[0], t);
    float Gosd = t + B[0];
    t = A[1] + C[1];
    float Gsds = fmaf(2.f, B[1], t);
    float Gods = t + B[1];
    t = A[2] + C[2];
    float Gsod = fmaf(2.f, B[2], t);
    t = A[3] + C[3];
    float Gsdo = fmaf(2.f, B[3], t);
    float Gdss = C[4] - A[4];
    float Gdos = C[5] - A[5];
    float Gdso = C[6] - A[6];
    float s1 = Gssd * Gssd;
    s1 = fmaf(Gsds, Gsds, s1);
    s1 = fmaf(Gdss, Gdss, s1);
    float s2 = Gsod * Gsod;
    s2 = fmaf(Gsdo, Gsdo, s2);
    s2 = fmaf(Gosd, Gosd, s2);
    s2 = fmaf(Gods, Gods, s2);
    s2 = fmaf(Gdso, Gdso, s2);
    s2 = fmaf(Gdos, Gdos, s2);
    float s = fmaf(2.f, s2, s1) + 1e-12f;
    return 0.5f * (s * rsqrtf(s));   // 0.5 * sqrt(s)
}

__device__ __forceinline__ void loadPlane(float* __restrict__ sA, float* __restrict__ sB,
                                          const float* __restrict__ Y,
                                          const float* __restrict__ P,
                                          long bOff, int z, int y0, int x0, int tid) {
    bool zin = (z >= 0) && (z < NDIM);
    const float* Yz = Y + bOff + (long)z * PLANE;
    const float* Pz = P + bOff + (long)z * PLANE;
    #pragma unroll
    for (int idx = tid; idx < COLH * ROWL; idx += NTHREADS) {
        int yy = idx / ROWL;
        int xx = idx - yy * ROWL;
        int gy = y0 + yy - 1;
        int gx = x0 + xx - 1;
        float vA = 0.f, vB = 0.f;
        if (zin && (unsigned)gy < (unsigned)NDIM && (unsigned)gx < (unsigned)NDIM) {
            int off = gy * NDIM + gx;
            vA = Yz[off] + Yz[off + CS];   // channel sum
            vB = Pz[off] + Pz[off + CS];
        }
        sA[idx] = vA;
        sB[idx] = vB;
    }
}

__global__ __launch_bounds__(NTHREADS, 1)
void gme_kernel(const float* __restrict__ Y, const float* __restrict__ P) {
    __shared__ float sA[COLH * ROWL];
    __shared__ float sB[COLH * ROWL];
    __shared__ float wsum[NTHREADS / 32];

    int tx = threadIdx.x, ty = threadIdx.y;
    int tid = ty * TX + tx;
    int x0 = blockIdx.x * TX;
    int y0 = blockIdx.y * TY;
    int zb = blockIdx.z;
    int b = zb >> 2;               // 128/ZC = 4 chunks per batch
    int z0 = (zb & 3) * ZC;
    long bOff = (long)b * 2 * CS;  // batch stride = C * 128^3

    float HAy[7], HBy[7], HCy[7];
    float HAp[7], HBp[7], HCp[7];
    float acc = 0.f;

#define STEP(HY, HP, zz) do {                              \
        __syncthreads();                                   \
        loadPlane(sA, sB, Y, P, bOff, (zz), y0, x0, tid);  \
        __syncthreads();                                   \
        computeH(sA, ty, tx, HY);                          \
        computeH(sB, ty, tx, HP);                          \
    } while (0)

#define EMIT(Ay, By, Cy, Ap, Bp, Cp) do {                  \
        float ey = edgeFromH(Ay, By, Cy);                  \
        float ep = edgeFromH(Ap, Bp, Cp);                  \
        float dd = ey - ep;                                \
        acc = fmaf(dd, dd, acc);                           \
    } while (0)

    STEP(HAy, HAp, z0 - 1);
    STEP(HBy, HBp, z0);
    int zz = z0 + 1;
    #pragma unroll 1
    for (int k = 0; k < 30; k += 3) {
        STEP(HCy, HCp, zz); EMIT(HAy, HBy, HCy, HAp, HBp, HCp); zz++;
        STEP(HAy, HAp, zz); EMIT(HBy, HCy, HAy, HBp, HCp, HAp); zz++;
        STEP(HBy, HBp, zz); EMIT(HCy, HAy, HBy, HCp, HAp, HBp); zz++;
    }
    // 2 remaining outputs (ZC=32 = 10*3 + 2)
    STEP(HCy, HCp, zz); EMIT(HAy, HBy, HCy, HAp, HBp, HCp); zz++;
    STEP(HAy, HAp, zz); EMIT(HBy, HCy, HAy, HBp, HCp, HAp);

#undef STEP
#undef EMIT

    // block reduction
    #pragma unroll
    for (int o = 16; o; o >>= 1)
        acc += __shfl_down_sync(0xffffffffu, acc, o);
    int lane = tid & 31, wid = tid >> 5;
    if (lane == 0) wsum[wid] = acc;
    __syncthreads();
    if (wid == 0) {
        float v = (lane < NTHREADS / 32) ? wsum[lane] : 0.f;
        #pragma unroll
        for (int o = 8; o; o >>= 1)
            v += __shfl_down_sync(0xffffffffu, v, o);
        if (lane == 0) atomicAdd(&g_acc, (double)v);
    }
}

__global__ void finalize_kernel(float* out, int n) {
    float m = (float)(g_acc / 4194304.0);   // mean over 2*1*128^3 outputs
    for (int i = 0; i < n; i++) out[i] = m;
}

extern "C" void kernel_launch(void* const* d_in, const int* in_sizes, int n_in,
                              void* d_out, int out_size) {
    const float* Y = (const float*)d_in[0];
    const float* P = (const float*)d_in[1];
    zero_acc_kernel<<<1, 1>>>();
    dim3 grid(NDIM / TX, NDIM / TY, (NDIM / ZC) * 2);
    dim3 blk(TX, TY);
    gme_kernel<<<grid, blk>>>(Y, P);
    finalize_kernel<<<1, 1>>>((float*)d_out, out_size);
}

// round 6
// speedup vs baseline: 1.4620x; 1.4620x over previous
#include <cuda_runtime.h>

#define TX 32
#define TY 16
#define ZC 32
#define NDIM 128
#define PLANE 16384          // 128*128
#define CS 2097152           // 128^3 (channel stride)
#define ROWL 34              // TX+2
#define COLH 18              // TY+2
#define NSLOT (ROWL*COLH)    // 612
#define NTHREADS (TX*TY)

__device__ double g_acc;

__global__ void zero_acc_kernel() { g_acc = 0.0; }

// Compute the 7 2D-filtered values at (ty,tx) from a halo plane in smem.
// s=[1,2,1], d=[-1,0,1], o=[1,1,1]
// H[0]=s_y d_x  H[1]=d_y s_x  H[2]=o_y d_x  H[3]=d_y o_x
// H[4]=s_y s_x  H[5]=o_y s_x  H[6]=s_y o_x
__device__ __forceinline__ void computeH(const float* __restrict__ sm,
                                         int base, float* H) {
    const float* r0 = sm + base;
    const float* r1 = r0 + ROWL;
    const float* r2 = r1 + ROWL;
    float a00 = r0[0], a01 = r0[1], a02 = r0[2];
    float a10 = r1[0], a11 = r1[1], a12 = r1[2];
    float a20 = r2[0], a21 = r2[1], a22 = r2[2];
    float t0 = a00 + a20, t1 = a01 + a21, t2 = a02 + a22;
    float sc0 = fmaf(2.f, a10, t0), sc1 = fmaf(2.f, a11, t1), sc2 = fmaf(2.f, a12, t2);
    float oc0 = t0 + a10, oc1 = t1 + a11, oc2 = t2 + a12;
    float dc0 = a20 - a00, dc1 = a21 - a01, dc2 = a22 - a02;
    float td = dc0 + dc2, ts = sc0 + sc2, to = oc0 + oc2;
    H[0] = sc2 - sc0;
    H[1] = fmaf(2.f, dc1, td);
    H[2] = oc2 - oc0;
    H[3] = td + dc1;
    H[4] = fmaf(2.f, sc1, ts);
    H[5] = fmaf(2.f, oc1, to);
    H[6] = ts + sc1;
}

// Combine z-ring (A=z-1, B=z, C=z+1) into edge magnitude * 0.5 (C=2 channels).
__device__ __forceinline__ float edgeFromH(const float* A, const float* B, const float* C) {
    float t;
    t = A[0] + C[0];
    float Gssd = fmaf(2.f, B[0], t);
    float Gosd = t + B[0];
    t = A[1] + C[1];
    float Gsds = fmaf(2.f, B[1], t);
    float Gods = t + B[1];
    t = A[2] + C[2];
    float Gsod = fmaf(2.f, B[2], t);
    t = A[3] + C[3];
    float Gsdo = fmaf(2.f, B[3], t);
    float Gdss = C[4] - A[4];
    float Gdos = C[5] - A[5];
    float Gdso = C[6] - A[6];
    float s1 = Gssd * Gssd;
    s1 = fmaf(Gsds, Gsds, s1);
    s1 = fmaf(Gdss, Gdss, s1);
    float s2 = Gsod * Gsod;
    s2 = fmaf(Gsdo, Gsdo, s2);
    s2 = fmaf(Gosd, Gosd, s2);
    s2 = fmaf(Gods, Gods, s2);
    s2 = fmaf(Gdso, Gdso, s2);
    s2 = fmaf(Gdos, Gdos, s2);
    float s = fmaf(2.f, s2, s1) + 1e-12f;
    return 0.5f * (s * rsqrtf(s));   // 0.5 * sqrt(s)
}

__global__ __launch_bounds__(NTHREADS, 1)
void gme_kernel(const float* __restrict__ Y, const float* __restrict__ P) {
    __shared__ float sA0[NSLOT], sB0[NSLOT];
    __shared__ float sA1[NSLOT], sB1[NSLOT];
    __shared__ float wsum[NTHREADS / 32];

    int tx = threadIdx.x, ty = threadIdx.y;
    int tid = ty * TX + tx;
    int x0 = blockIdx.x * TX;
    int y0 = blockIdx.y * TY;
    int zb = blockIdx.z;
    int b = zb >> 2;               // 128/ZC = 4 chunks per batch
    int z0 = (zb & 3) * ZC;
    const float* Yb = Y + (long)b * 2 * CS;
    const float* Pb = P + (long)b * 2 * CS;

    // ---- plane-invariant halo addressing (computed once) ----
    // slot0 = tid, slot1 = tid + 512 (exists iff tid < NSLOT-512 = 100)
    int yy0 = tid / ROWL, xx0 = tid - yy0 * ROWL;
    int gy0 = y0 + yy0 - 1, gx0 = x0 + xx0 - 1;
    bool m0 = ((unsigned)gy0 < NDIM) && ((unsigned)gx0 < NDIM);
    int off0 = (m0 ? gy0 * NDIM + gx0 : 0);

    int t1i = tid + NTHREADS;
    bool has1 = (t1i < NSLOT);
    int yy1 = t1i / ROWL, xx1 = t1i - yy1 * ROWL;
    int gy1 = y0 + yy1 - 1, gx1 = x0 + xx1 - 1;
    bool m1 = has1 && ((unsigned)gy1 < NDIM) && ((unsigned)gx1 < NDIM);
    int off1 = (m1 ? gy1 * NDIM + gx1 : 0);

    int hbase = ty * ROWL + tx;    // computeH anchor

    float rA0, rB0, rA1, rB1;

#define PREF(zz) do {                                              \
        int _z = (zz);                                             \
        bool zin = ((unsigned)_z < NDIM);                          \
        const float* Yz = Yb + _z * PLANE;                         \
        const float* Pz = Pb + _z * PLANE;                         \
        rA0 = rB0 = rA1 = rB1 = 0.f;                               \
        if (zin) {                                                 \
            if (m0) { rA0 = Yz[off0] + Yz[off0 + CS];              \
                      rB0 = Pz[off0] + Pz[off0 + CS]; }            \
            if (m1) { rA1 = Yz[off1] + Yz[off1 + CS];              \
                      rB1 = Pz[off1] + Pz[off1 + CS]; }            \
        }                                                          \
    } while (0)

    float *cA = sA0, *cB = sB0, *nA = sA1, *nB = sB1;

    // STEP: commit prefetched regs to the "next" buffers, barrier, swap,
    // issue prefetch for plane zpre (loads fly during compute), compute H.
#define STEP(HY, HP, zpre, DO_PF) do {                             \
        nA[tid] = rA0; nB[tid] = rB0;                              \
        if (has1) { nA[t1i] = rA1; nB[t1i] = rB1; }                \
        __syncthreads();                                           \
        { float* t = cA; cA = nA; nA = t; }                        \
        { float* t = cB; cB = nB; nB = t; }                        \
        if (DO_PF) PREF(zpre);                                     \
        computeH(cA, hbase, HY);                                   \
        computeH(cB, hbase, HP);                                   \
    } while (0)

#define EMIT(Ay, By, Cy, Ap, Bp, Cp) do {                          \
        float ey = edgeFromH(Ay, By, Cy);                          \
        float ep = edgeFromH(Ap, Bp, Cp);                          \
        float dd = ey - ep;                                        \
        acc = fmaf(dd, dd, acc);                                   \
    } while (0)

    float HAy[7], HBy[7], HCy[7];
    float HAp[7], HBp[7], HCp[7];
    float acc = 0.f;

    PREF(z0 - 1);
    STEP(HAy, HAp, z0, 1);
    STEP(HBy, HBp, z0 + 1, 1);
    int zz = z0 + 2;
    #pragma unroll 1
    for (int k = 0; k < 30; k += 3) {
        STEP(HCy, HCp, zz, 1); EMIT(HAy, HBy, HCy, HAp, HBp, HCp); zz++;
        STEP(HAy, HAp, zz, 1); EMIT(HBy, HCy, HAy, HBp, HCp, HAp); zz++;
        STEP(HBy, HBp, zz, 1); EMIT(HCy, HAy, HBy, HCp, HAp, HBp); zz++;
    }
    // remaining 2 planes / outputs (ZC+2 = 34 planes total, 32 outputs)
    STEP(HCy, HCp, zz, 1); EMIT(HAy, HBy, HCy, HAp, HBp, HCp);
    STEP(HAy, HAp, 0, 0);  EMIT(HBy, HCy, HAy, HBp, HCp, HAp);

#undef STEP
#undef EMIT
#undef PREF

    // block reduction
    #pragma unroll
    for (int o = 16; o; o >>= 1)
        acc += __shfl_down_sync(0xffffffffu, acc, o);
    int lane = tid & 31, wid = tid >> 5;
    if (lane == 0) wsum[wid] = acc;
    __syncthreads();
    if (wid == 0) {
        float v = (lane < NTHREADS / 32) ? wsum[lane] : 0.f;
        #pragma unroll
        for (int o = 8; o; o >>= 1)
            v += __shfl_down_sync(0xffffffffu, v, o);
        if (lane == 0) atomicAdd(&g_acc, (double)v);
    }
}

__global__ void finalize_kernel(float* out, int n) {
    float m = (float)(g_acc / 4194304.0);   // mean over 2*1*128^3 outputs
    for (int i = 0; i < n; i++) out[i] = m;
}

extern "C" void kernel_launch(void* const* d_in, const int* in_sizes, int n_in,
                              void* d_out, int out_size) {
    const float* Y = (const float*)d_in[0];
    const float* P = (const float*)d_in[1];
    zero_acc_kernel<<<1, 1>>>();
    dim3 grid(NDIM / TX, NDIM / TY, (NDIM / ZC) * 2);
    dim3 blk(TX, TY);
    gme_kernel<<<grid, blk>>>(Y, P);
    finalize_kernel<<<1, 1>>>((float*)d_out, out_size);
}

// round 7
// speedup vs baseline: 1.6142x; 1.1041x over previous
#include <cuda_runtime.h>

#define TX 32
#define TY 8
#define ZC 32
#define NDIM 128
#define PLANE 16384          // 128*128
#define CS 2097152           // 128^3 (channel stride)
#define ROWL 34              // TX+2
#define COLH 10              // TY+2
#define NSLOT (ROWL*COLH)    // 340
#define NTHREADS (TX*TY)     // 256
#define NBLOCKS 512          // 4 * 16 * 8

__device__ double g_acc;          // zero-initialized at module load; self-resetting
__device__ unsigned int g_cnt;    // ditto

// Compute the 7 2D-filtered values at (ty,tx) from a halo plane in smem.
// s=[1,2,1], d=[-1,0,1], o=[1,1,1]
// H[0]=s_y d_x  H[1]=d_y s_x  H[2]=o_y d_x  H[3]=d_y o_x
// H[4]=s_y s_x  H[5]=o_y s_x  H[6]=s_y o_x
__device__ __forceinline__ void computeH(const float* __restrict__ sm,
                                         int base, float* H) {
    const float* r0 = sm + base;
    const float* r1 = r0 + ROWL;
    const float* r2 = r1 + ROWL;
    float a00 = r0[0], a01 = r0[1], a02 = r0[2];
    float a10 = r1[0], a11 = r1[1], a12 = r1[2];
    float a20 = r2[0], a21 = r2[1], a22 = r2[2];
    float t0 = a00 + a20, t1 = a01 + a21, t2 = a02 + a22;
    float sc0 = fmaf(2.f, a10, t0), sc1 = fmaf(2.f, a11, t1), sc2 = fmaf(2.f, a12, t2);
    float oc0 = t0 + a10, oc1 = t1 + a11, oc2 = t2 + a12;
    float dc0 = a20 - a00, dc1 = a21 - a01, dc2 = a22 - a02;
    float td = dc0 + dc2, ts = sc0 + sc2, to = oc0 + oc2;
    H[0] = sc2 - sc0;
    H[1] = fmaf(2.f, dc1, td);
    H[2] = oc2 - oc0;
    H[3] = td + dc1;
    H[4] = fmaf(2.f, sc1, ts);
    H[5] = fmaf(2.f, oc1, to);
    H[6] = ts + sc1;
}

// Combine z-ring (A=z-1, B=z, C=z+1) into edge magnitude * 0.5 (C=2 channels).
__device__ __forceinline__ float edgeFromH(const float* A, const float* B, const float* C) {
    float t;
    t = A[0] + C[0];
    float Gssd = fmaf(2.f, B[0], t);
    float Gosd = t + B[0];
    t = A[1] + C[1];
    float Gsds = fmaf(2.f, B[1], t);
    float Gods = t + B[1];
    t = A[2] + C[2];
    float Gsod = fmaf(2.f, B[2], t);
    t = A[3] + C[3];
    float Gsdo = fmaf(2.f, B[3], t);
    float Gdss = C[4] - A[4];
    float Gdos = C[5] - A[5];
    float Gdso = C[6] - A[6];
    float s1 = Gssd * Gssd;
    s1 = fmaf(Gsds, Gsds, s1);
    s1 = fmaf(Gdss, Gdss, s1);
    float s2 = Gsod * Gsod;
    s2 = fmaf(Gsdo, Gsdo, s2);
    s2 = fmaf(Gosd, Gosd, s2);
    s2 = fmaf(Gods, Gods, s2);
    s2 = fmaf(Gdso, Gdso, s2);
    s2 = fmaf(Gdos, Gdos, s2);
    float s = fmaf(2.f, s2, s1) + 1e-12f;
    return 0.5f * (s * rsqrtf(s));   // 0.5 * sqrt(s)
}

__global__ __launch_bounds__(NTHREADS, 2)
void gme_kernel(const float* __restrict__ Y, const float* __restrict__ P,
                float* __restrict__ out, int out_n) {
    __shared__ float sA0[NSLOT], sB0[NSLOT];
    __shared__ float sA1[NSLOT], sB1[NSLOT];
    __shared__ float wsum[NTHREADS / 32];

    int tx = threadIdx.x, ty = threadIdx.y;
    int tid = ty * TX + tx;
    int x0 = blockIdx.x * TX;
    int y0 = blockIdx.y * TY;
    int zb = blockIdx.z;
    int b = zb >> 2;               // 128/ZC = 4 chunks per batch
    int z0 = (zb & 3) * ZC;
    const float* Yb = Y + (long)b * 2 * CS;
    const float* Pb = P + (long)b * 2 * CS;

    // ---- plane-invariant halo addressing (computed once) ----
    int yy0 = tid / ROWL, xx0 = tid - yy0 * ROWL;
    int gy0 = y0 + yy0 - 1, gx0 = x0 + xx0 - 1;
    bool m0 = ((unsigned)gy0 < NDIM) && ((unsigned)gx0 < NDIM);
    int off0 = (m0 ? gy0 * NDIM + gx0 : 0);

    int t1i = tid + NTHREADS;
    bool has1 = (t1i < NSLOT);     // tid < 84
    int yy1 = t1i / ROWL, xx1 = t1i - yy1 * ROWL;
    int gy1 = y0 + yy1 - 1, gx1 = x0 + xx1 - 1;
    bool m1 = has1 && ((unsigned)gy1 < NDIM) && ((unsigned)gx1 < NDIM);
    int off1 = (m1 ? gy1 * NDIM + gx1 : 0);

    int hbase = ty * ROWL + tx;    // computeH anchor

    float rA0, rB0, rA1, rB1;

#define PREF(zz) do {                                              \
        int _z = (zz);                                             \
        bool zin = ((unsigned)_z < NDIM);                          \
        const float* Yz = Yb + _z * PLANE;                         \
        const float* Pz = Pb + _z * PLANE;                         \
        rA0 = rB0 = rA1 = rB1 = 0.f;                               \
        if (zin) {                                                 \
            if (m0) { rA0 = Yz[off0] + Yz[off0 + CS];              \
                      rB0 = Pz[off0] + Pz[off0 + CS]; }            \
            if (m1) { rA1 = Yz[off1] + Yz[off1 + CS];              \
                      rB1 = Pz[off1] + Pz[off1 + CS]; }            \
        }                                                          \
    } while (0)

    float *cA = sA0, *cB = sB0, *nA = sA1, *nB = sB1;

#define STEP(HY, HP, zpre, DO_PF) do {                             \
        nA[tid] = rA0; nB[tid] = rB0;                              \
        if (has1) { nA[t1i] = rA1; nB[t1i] = rB1; }                \
        __syncthreads();                                           \
        { float* t = cA; cA = nA; nA = t; }                        \
        { float* t = cB; cB = nB; nB = t; }                        \
        if (DO_PF) PREF(zpre);                                     \
        computeH(cA, hbase, HY);                                   \
        computeH(cB, hbase, HP);                                   \
    } while (0)

#define EMIT(Ay, By, Cy, Ap, Bp, Cp) do {                          \
        float ey = edgeFromH(Ay, By, Cy);                          \
        float ep = edgeFromH(Ap, Bp, Cp);                          \
        float dd = ey - ep;                                        \
        acc = fmaf(dd, dd, acc);                                   \
    } while (0)

    float HAy[7], HBy[7], HCy[7];
    float HAp[7], HBp[7], HCp[7];
    float acc = 0.f;

    PREF(z0 - 1);
    STEP(HAy, HAp, z0, 1);
    STEP(HBy, HBp, z0 + 1, 1);
    int zz = z0 + 2;
    #pragma unroll 1
    for (int k = 0; k < 30; k += 3) {
        STEP(HCy, HCp, zz, 1); EMIT(HAy, HBy, HCy, HAp, HBp, HCp); zz++;
        STEP(HAy, HAp, zz, 1); EMIT(HBy, HCy, HAy, HBp, HCp, HAp); zz++;
        STEP(HBy, HBp, zz, 1); EMIT(HCy, HAy, HBy, HCp, HAp, HBp); zz++;
    }
    // remaining 2 planes / outputs (ZC+2 = 34 planes total, 32 outputs)
    STEP(HCy, HCp, zz, 1); EMIT(HAy, HBy, HCy, HAp, HBp, HCp);
    STEP(HAy, HAp, 0, 0);  EMIT(HBy, HCy, HAy, HBp, HCp, HAp);

#undef STEP
#undef EMIT
#undef PREF

    // block reduction
    #pragma unroll
    for (int o = 16; o; o >>= 1)
        acc += __shfl_down_sync(0xffffffffu, acc, o);
    int lane = tid & 31, wid = tid >> 5;
    if (lane == 0) wsum[wid] = acc;
    __syncthreads();
    if (wid == 0) {
        float v = (lane < NTHREADS / 32) ? wsum[lane] : 0.f;
        #pragma unroll
        for (int o = 4; o; o >>= 1)
            v += __shfl_down_sync(0xffffffffu, v, o);
        if (lane == 0) {
            atomicAdd(&g_acc, (double)v);
            __threadfence();
            unsigned done = atomicAdd(&g_cnt, 1u);
            if (done == NBLOCKS - 1) {
                // last block: all g_acc contributions visible (fence + atomic chain)
                float m = (float)(g_acc / 4194304.0);   // mean over 2*1*128^3
                for (int i = 0; i < out_n; i++) out[i] = m;
                // self-reset for the next (graph-replayed) call
                g_acc = 0.0;
                __threadfence();
                g_cnt = 0u;
            }
        }
    }
}

extern "C" void kernel_launch(void* const* d_in, const int* in_sizes, int n_in,
                              void* d_out, int out_size) {
    const float* Y = (const float*)d_in[0];
    const float* P = (const float*)d_in[1];
    dim3 grid(NDIM / TX, NDIM / TY, (NDIM / ZC) * 2);  // 4 x 16 x 8 = 512
    dim3 blk(TX, TY);
    gme_kernel<<<grid, blk>>>(Y, P, (float*)d_out, out_size);
}

// round 9
// speedup vs baseline: 1.7021x; 1.0545x over previous
#include <cuda_runtime.h>

#define NDIM 128
#define PLANE 16384          // 128*128
#define CS 2097152           // 128^3 (channel stride)
#define TVX 16               // tile voxels in x
#define TVY 8                // tile voxels in y
#define ZC 32
#define ROWL 18              // TVX+2
#define COLH 10              // TVY+2
#define NSLOT (ROWL*COLH)    // 180 per volume
#define VSTR 208             // smem stride between volumes (==16 mod 32: bank-disjoint halves)
#define TOTSLOT (2*NSLOT)    // 360
#define NTHREADS 256
#define NBLOCKS 1024         // 8 * 16 * 8

__device__ double g_acc;          // zero-init at load; self-resetting
__device__ unsigned int g_cnt;    // ditto

// 7 2D-filtered values at (row=base) from a halo plane in smem.
// s=[1,2,1], d=[-1,0,1], o=[1,1,1]
// H[0]=s_y d_x  H[1]=d_y s_x  H[2]=o_y d_x  H[3]=d_y o_x
// H[4]=s_y s_x  H[5]=o_y s_x  H[6]=s_y o_x
__device__ __forceinline__ void computeH(const float* __restrict__ sm,
                                         int base, float* H) {
    const float* r0 = sm + base;
    const float* r1 = r0 + ROWL;
    const float* r2 = r1 + ROWL;
    float a00 = r0[0], a01 = r0[1], a02 = r0[2];
    float a10 = r1[0], a11 = r1[1], a12 = r1[2];
    float a20 = r2[0], a21 = r2[1], a22 = r2[2];
    float t0 = a00 + a20, t1 = a01 + a21, t2 = a02 + a22;
    float sc0 = fmaf(2.f, a10, t0), sc1 = fmaf(2.f, a11, t1), sc2 = fmaf(2.f, a12, t2);
    float oc0 = t0 + a10, oc1 = t1 + a11, oc2 = t2 + a12;
    float dc0 = a20 - a00, dc1 = a21 - a01, dc2 = a22 - a02;
    float td = dc0 + dc2, ts = sc0 + sc2, to = oc0 + oc2;
    H[0] = sc2 - sc0;
    H[1] = fmaf(2.f, dc1, td);
    H[2] = oc2 - oc0;
    H[3] = td + dc1;
    H[4] = fmaf(2.f, sc1, ts);
    H[5] = fmaf(2.f, oc1, to);
    H[6] = ts + sc1;
}

// Combine z-ring (A=z-1, B=z, C=z+1) into edge magnitude * 0.5 (C=2 channels).
__device__ __forceinline__ float edgeFromH(const float* A, const float* B, const float* C) {
    float t;
    t = A[0] + C[0];
    float Gssd = fmaf(2.f, B[0], t);
    float Gosd = t + B[0];
    t = A[1] + C[1];
    float Gsds = fmaf(2.f, B[1], t);
    float Gods = t + B[1];
    t = A[2] + C[2];
    float Gsod = fmaf(2.f, B[2], t);
    t = A[3] + C[3];
    float Gsdo = fmaf(2.f, B[3], t);
    float Gdss = C[4] - A[4];
    float Gdos = C[5] - A[5];
    float Gdso = C[6] - A[6];
    float s1 = Gssd * Gssd;
    s1 = fmaf(Gsds, Gsds, s1);
    s1 = fmaf(Gdss, Gdss, s1);
    float s2 = Gsod * Gsod;
    s2 = fmaf(Gsdo, Gsdo, s2);
    s2 = fmaf(Gosd, Gosd, s2);
    s2 = fmaf(Gods, Gods, s2);
    s2 = fmaf(Gdso, Gdso, s2);
    s2 = fmaf(Gdos, Gdos, s2);
    float s = fmaf(2.f, s2, s1) + 1e-12f;
    return 0.5f * (s * rsqrtf(s));   // 0.5 * sqrt(s)
}

__global__ __launch_bounds__(NTHREADS, 3)
void gme_kernel(const float* __restrict__ Y, const float* __restrict__ P,
                float* __restrict__ out, int out_n) {
    __shared__ float sm0[2 * VSTR];
    __shared__ float sm1[2 * VSTR];
    __shared__ float wsum[NTHREADS / 32];

    int lane = threadIdx.x;            // 0..31
    int ty = threadIdx.y;              // 0..7
    int tid = ty * 32 + lane;
    int vol = lane >> 4;               // 0 = Y, 1 = P
    int lx = lane & 15;
    int x0 = blockIdx.x * TVX;
    int y0 = blockIdx.y * TVY;
    int zb = blockIdx.z;
    int b = zb >> 2;                   // 4 z-chunks per batch
    int z0 = (zb & 3) * ZC;
    const float* Yb = Y + (long)b * 2 * CS;
    const float* Pb = P + (long)b * 2 * CS;

    // ---- plane-invariant halo addressing ----
    // slot0 = tid (0..255): volume = tid>=180 ? P : Y
    int v0 = (tid >= NSLOT) ? 1 : 0;
    int r0i = tid - v0 * NSLOT;
    int yy0 = r0i / ROWL, xx0 = r0i - yy0 * ROWL;
    int gy0 = y0 + yy0 - 1, gx0 = x0 + xx0 - 1;
    bool m0 = ((unsigned)gy0 < NDIM) && ((unsigned)gx0 < NDIM);
    const float* bp0 = (v0 ? Pb : Yb) + (m0 ? gy0 * NDIM + gx0 : 0);
    int si0 = v0 * VSTR + r0i;

    // slot1 = tid + 256 (exists iff tid < 104); always volume P (256 >= 180)
    bool has1 = (tid < TOTSLOT - NTHREADS);        // tid < 104
    int r1i = tid + (NTHREADS - NSLOT);            // tid + 76
    int yy1 = r1i / ROWL, xx1 = r1i - yy1 * ROWL;
    int gy1 = y0 + yy1 - 1, gx1 = x0 + xx1 - 1;
    bool m1 = has1 && ((unsigned)gy1 < NDIM) && ((unsigned)gx1 < NDIM);
    const float* bp1 = Pb + (m1 ? gy1 * NDIM + gx1 : 0);
    int si1 = VSTR + r1i;

    int hbase = vol * VSTR + ty * ROWL + lx;       // computeH anchor

    float rA, rB;

#define PREF(zz) do {                                              \
        int _z = (zz);                                             \
        bool zin = ((unsigned)_z < NDIM);                          \
        int zoff = _z * PLANE;                                     \
        rA = 0.f; rB = 0.f;                                        \
        if (zin) {                                                 \
            if (m0) rA = bp0[zoff] + bp0[zoff + CS];               \
            if (m1) rB = bp1[zoff] + bp1[zoff + CS];               \
        }                                                          \
    } while (0)

    float *cS = sm0, *nS = sm1;

#define STEP(HH, zpre, DO_PF) do {                                 \
        nS[si0] = rA;                                              \
        if (has1) nS[si1] = rB;                                    \
        __syncthreads();                                           \
        { float* t = cS; cS = nS; nS = t; }                        \
        if (DO_PF) PREF(zpre);                                     \
        computeH(cS, hbase, HH);                                   \
    } while (0)

#define EMIT(A, B, C) do {                                         \
        float e = edgeFromH(A, B, C);                              \
        float eo = __shfl_xor_sync(0xffffffffu, e, 16);            \
        float dd = e - eo;                                         \
        acc = fmaf(dd, dd, acc);                                   \
    } while (0)

    float HA[7], HB[7], HC[7];
    float acc = 0.f;

    PREF(z0 - 1);
    STEP(HA, z0, 1);
    STEP(HB, z0 + 1, 1);
    int zz = z0 + 2;
    #pragma unroll 1
    for (int k = 0; k < 30; k += 3) {
        STEP(HC, zz, 1); EMIT(HA, HB, HC); zz++;
        STEP(HA, zz, 1); EMIT(HB, HC, HA); zz++;
        STEP(HB, zz, 1); EMIT(HC, HA, HB); zz++;
    }
    // remaining 2 planes / outputs (ZC+2 = 34 planes, 32 outputs)
    STEP(HC, zz, 1); EMIT(HA, HB, HC);
    STEP(HA, 0, 0);  EMIT(HB, HC, HA);

#undef STEP
#undef EMIT
#undef PREF

    // block reduction (both half-warps contribute dd^2 -> double-counted; fixed in mean)
    #pragma unroll
    for (int o = 16; o; o >>= 1)
        acc += __shfl_down_sync(0xffffffffu, acc, o);
    int l32 = tid & 31, wid = tid >> 5;
    if (l32 == 0) wsum[wid] = acc;
    __syncthreads();
    if (wid == 0) {
        float v = (l32 < NTHREADS / 32) ? wsum[l32] : 0.f;
        #pragma unroll
        for (int o = 4; o; o >>= 1)
            v += __shfl_down_sync(0xffffffffu, v, o);
        if (l32 == 0) {
            atomicAdd(&g_acc, (double)v);
            __threadfence();
            unsigned done = atomicAdd(&g_cnt, 1u);
            if (done == NBLOCKS - 1) {
                // mean over 2*128^3 outputs, /2 for the double count
                float m = (float)(g_acc / 8388608.0);
                for (int i = 0; i < out_n; i++) out[i] = m;
                g_acc = 0.0;
                __threadfence();
                g_cnt = 0u;
            }
        }
    }
}

extern "C" void kernel_launch(void* const* d_in, const int* in_sizes, int n_in,
                              void* d_out, int out_size) {
    const float* Y = (const float*)d_in[0];
    const float* P = (const float*)d_in[1];
    dim3 grid(NDIM / TVX, NDIM / TVY, (NDIM / ZC) * 2);  // 8 x 16 x 8 = 1024
    dim3 blk(32, 8);
    gme_kernel<<<grid, blk>>>(Y, P, (float*)d_out, out_size);
}

// round 10
// speedup vs baseline: 1.8132x; 1.0653x over previous
#include <cuda_runtime.h>

#define NDIM 128
#define PLANE 16384          // 128*128
#define CS 2097152           // 128^3 (channel stride)
#define TVX 16               // tile voxels in x
#define TVY 8                // tile voxels in y
#define ZC 32
#define ROWL 18              // TVX+2
#define COLH 10              // TVY+2
#define NSLOT (ROWL*COLH)    // 180 per volume
#define VSTR 208             // smem stride between volumes (==16 mod 32: bank-disjoint halves)
#define TOTSLOT (2*NSLOT)    // 360
#define NTHREADS 256
#define NBLOCKS 1024         // 8 * 16 * 8

__device__ double g_acc;          // zero-init at load; self-resetting
__device__ unsigned int g_cnt;    // ditto

// 7 2D-filtered values at (row=base) from a halo plane in smem.
// s=[1,2,1], d=[-1,0,1], o=[1,1,1]
// H[0]=s_y d_x  H[1]=d_y s_x  H[2]=o_y d_x  H[3]=d_y o_x
// H[4]=s_y s_x  H[5]=o_y s_x  H[6]=s_y o_x
__device__ __forceinline__ void computeH(const float* __restrict__ sm,
                                         int base, float* H) {
    const float* r0 = sm + base;
    const float* r1 = r0 + ROWL;
    const float* r2 = r1 + ROWL;
    float a00 = r0[0], a01 = r0[1], a02 = r0[2];
    float a10 = r1[0], a11 = r1[1], a12 = r1[2];
    float a20 = r2[0], a21 = r2[1], a22 = r2[2];
    float t0 = a00 + a20, t1 = a01 + a21, t2 = a02 + a22;
    float sc0 = fmaf(2.f, a10, t0), sc1 = fmaf(2.f, a11, t1), sc2 = fmaf(2.f, a12, t2);
    float oc0 = t0 + a10, oc1 = t1 + a11, oc2 = t2 + a12;
    float dc0 = a20 - a00, dc1 = a21 - a01, dc2 = a22 - a02;
    float td = dc0 + dc2, ts = sc0 + sc2, to = oc0 + oc2;
    H[0] = sc2 - sc0;
    H[1] = fmaf(2.f, dc1, td);
    H[2] = oc2 - oc0;
    H[3] = td + dc1;
    H[4] = fmaf(2.f, sc1, ts);
    H[5] = fmaf(2.f, oc1, to);
    H[6] = ts + sc1;
}

// Combine z-ring (A=z-1, B=z, C=z+1) into edge magnitude * 0.5 (C=2 channels).
__device__ __forceinline__ float edgeFromH(const float* A, const float* B, const float* C) {
    float t;
    t = A[0] + C[0];
    float Gssd = fmaf(2.f, B[0], t);
    float Gosd = t + B[0];
    t = A[1] + C[1];
    float Gsds = fmaf(2.f, B[1], t);
    float Gods = t + B[1];
    t = A[2] + C[2];
    float Gsod = fmaf(2.f, B[2], t);
    t = A[3] + C[3];
    float Gsdo = fmaf(2.f, B[3], t);
    float Gdss = C[4] - A[4];
    float Gdos = C[5] - A[5];
    float Gdso = C[6] - A[6];
    float s1 = Gssd * Gssd;
    s1 = fmaf(Gsds, Gsds, s1);
    s1 = fmaf(Gdss, Gdss, s1);
    float s2 = Gsod * Gsod;
    s2 = fmaf(Gsdo, Gsdo, s2);
    s2 = fmaf(Gosd, Gosd, s2);
    s2 = fmaf(Gods, Gods, s2);
    s2 = fmaf(Gdso, Gdso, s2);
    s2 = fmaf(Gdos, Gdos, s2);
    float s = fmaf(2.f, s2, s1) + 1e-12f;
    return 0.5f * (s * rsqrtf(s));   // 0.5 * sqrt(s)
}

__global__ __launch_bounds__(NTHREADS, 4)
void gme_kernel(const float* __restrict__ Y, const float* __restrict__ P,
                float* __restrict__ out, int out_n) {
    __shared__ float sm0[2 * VSTR];
    __shared__ float sm1[2 * VSTR];
    __shared__ float wsum[NTHREADS / 32];

    int lane = threadIdx.x;            // 0..31
    int ty = threadIdx.y;              // 0..7
    int tid = ty * 32 + lane;
    int vol = lane >> 4;               // 0 = Y, 1 = P
    int lx = lane & 15;
    int x0 = blockIdx.x * TVX;
    int y0 = blockIdx.y * TVY;
    int zb = blockIdx.z;
    int b = zb >> 2;                   // 4 z-chunks per batch
    int z0 = (zb & 3) * ZC;
    const float* Yb = Y + (long)b * 2 * CS;
    const float* Pb = P + (long)b * 2 * CS;

    // ---- plane-invariant halo addressing ----
    // slot0 = tid (0..255): volume = tid>=180 ? P : Y
    int v0 = (tid >= NSLOT) ? 1 : 0;
    int r0i = tid - v0 * NSLOT;
    int yy0 = r0i / ROWL, xx0 = r0i - yy0 * ROWL;
    int gy0 = y0 + yy0 - 1, gx0 = x0 + xx0 - 1;
    bool m0 = ((unsigned)gy0 < NDIM) && ((unsigned)gx0 < NDIM);
    const float* bp0 = (v0 ? Pb : Yb) + (m0 ? gy0 * NDIM + gx0 : 0);
    int si0 = v0 * VSTR + r0i;

    // slot1 = tid + 256 (exists iff tid < 104); always volume P (256 >= 180)
    bool has1 = (tid < TOTSLOT - NTHREADS);        // tid < 104
    int r1i = tid + (NTHREADS - NSLOT);            // tid + 76
    int yy1 = r1i / ROWL, xx1 = r1i - yy1 * ROWL;
    int gy1 = y0 + yy1 - 1, gx1 = x0 + xx1 - 1;
    bool m1 = has1 && ((unsigned)gy1 < NDIM) && ((unsigned)gx1 < NDIM);
    const float* bp1 = Pb + (m1 ? gy1 * NDIM + gx1 : 0);
    int si1 = VSTR + r1i;

    int hbase = vol * VSTR + ty * ROWL + lx;       // computeH anchor

    float rA, rB;

#define PREF(zz) do {                                              \
        int _z = (zz);                                             \
        bool zin = ((unsigned)_z < NDIM);                          \
        int zoff = _z * PLANE;                                     \
        rA = 0.f; rB = 0.f;                                        \
        if (zin & m0) rA = bp0[zoff] + bp0[zoff + CS];             \
        if (zin & m1) rB = bp1[zoff] + bp1[zoff + CS];             \
    } while (0)

    float *cS = sm0, *nS = sm1;

#define STEP(HH, zpre, DO_PF) do {                                 \
        nS[si0] = rA;                                              \
        if (has1) nS[si1] = rB;                                    \
        __syncthreads();                                           \
        { float* t = cS; cS = nS; nS = t; }                        \
        if (DO_PF) PREF(zpre);                                     \
        computeH(cS, hbase, HH);                                   \
    } while (0)

#define EMIT(A, B, C) do {                                         \
        float e = edgeFromH(A, B, C);                              \
        float eo = __shfl_xor_sync(0xffffffffu, e, 16);            \
        float dd = e - eo;                                         \
        acc = fmaf(dd, dd, acc);                                   \
    } while (0)

    float HA[7], HB[7], HC[7];
    float acc = 0.f;

    PREF(z0 - 1);
    STEP(HA, z0, 1);
    STEP(HB, z0 + 1, 1);
    int zz = z0 + 2;
    #pragma unroll 1
    for (int k = 0; k < 30; k += 3) {
        STEP(HC, zz, 1); EMIT(HA, HB, HC); zz++;
        STEP(HA, zz, 1); EMIT(HB, HC, HA); zz++;
        STEP(HB, zz, 1); EMIT(HC, HA, HB); zz++;
    }
    // remaining 2 planes / outputs (ZC+2 = 34 planes, 32 outputs)
    STEP(HC, zz, 1); EMIT(HA, HB, HC);
    STEP(HA, 0, 0);  EMIT(HB, HC, HA);

#undef STEP
#undef EMIT
#undef PREF

    // block reduction (both half-warps contribute dd^2 -> double-counted; fixed in mean)
    #pragma unroll
    for (int o = 16; o; o >>= 1)
        acc += __shfl_down_sync(0xffffffffu, acc, o);
    int l32 = tid & 31, wid = tid >> 5;
    if (l32 == 0) wsum[wid] = acc;
    __syncthreads();
    if (wid == 0) {
        float v = (l32 < NTHREADS / 32) ? wsum[l32] : 0.f;
        #pragma unroll
        for (int o = 4; o; o >>= 1)
            v += __shfl_down_sync(0xffffffffu, v, o);
        if (l32 == 0) {
            atomicAdd(&g_acc, (double)v);
            __threadfence();
            unsigned done = atomicAdd(&g_cnt, 1u);
            if (done == NBLOCKS - 1) {
                // mean over 2*128^3 outputs, /2 for the double count
                float m = (float)(g_acc / 8388608.0);
                for (int i = 0; i < out_n; i++) out[i] = m;
                g_acc = 0.0;
                __threadfence();
                g_cnt = 0u;
            }
        }
    }
}

extern "C" void kernel_launch(void* const* d_in, const int* in_sizes, int n_in,
                              void* d_out, int out_size) {
    const float* Y = (const float*)d_in[0];
    const float* P = (const float*)d_in[1];
    dim3 grid(NDIM / TVX, NDIM / TVY, (NDIM / ZC) * 2);  // 8 x 16 x 8 = 1024
    dim3 blk(32, 8);
    gme_kernel<<<grid, blk>>>(Y, P, (float*)d_out, out_size);
}